// round 10
// baseline (speedup 1.0000x reference)
#include <cuda_runtime.h>
#include <cuda_bf16.h>
#include <cstdint>

#define NN 30000
#define TT 4
#define FF 128
#define HH 8
#define DD 16

// Scratch (no cudaMalloc allowed)
__device__ float g_node_p[NN * FF];        // [N,F]
__device__ int   g_lists[TT][NN];
__device__ int   g_counts[TT];

// ---------------------------------------------------------------------------
__global__ void k_zero() { if (threadIdx.x < TT) g_counts[threadIdx.x] = 0; }

__global__ void k_scatter(const int* __restrict__ mask, int n) {
    int i = blockIdx.x * blockDim.x + threadIdx.x;
    if (i < n) {
        int t = mask[i];
        int p = atomicAdd(&g_counts[t], 1);
        g_lists[t][p] = i;
    }
}

// ---------------------------------------------------------------------------
// GEMM core: C[i,g] = sum_f A[i,f]*M[g,f];  C = Ah*Mh + Al*Mh + Ah*Ml.
// 4 SMEM tiles 128x128 bf16, rows padded to 136 bf16 (272 B).
// 512 threads, 16 warps in 4(m) x 4(n); warp tile 32m x 32n; acc = 32 regs.
// ldmatrix.x4 fragment loads (numerics validated R4/R6/R7).
// ---------------------------------------------------------------------------
#define RSTRIDE 136
#define TILE_BYTES (128 * RSTRIDE * 2)    // 34816
#define SM_AHI 0
#define SM_ALO TILE_BYTES
#define SM_MHI (2 * TILE_BYTES)
#define SM_MLO (3 * TILE_BYTES)
#define SM_ROWS (4 * TILE_BYTES)          // 128 ints
#define SM_SCORE (SM_ROWS + 512)          // 128*8 floats
#define SMEM_BYTES (SM_SCORE + 4096)

__device__ __forceinline__ uint32_t pk(__nv_bfloat16 a, __nv_bfloat16 b) {
    __nv_bfloat162 t(a, b);
    return *(uint32_t*)&t;
}

__device__ __forceinline__ void split4(float4 v, uint2& hi, uint2& lo) {
    __nv_bfloat16 h0 = __float2bfloat16_rn(v.x); float l0 = v.x - __bfloat162float(h0);
    __nv_bfloat16 h1 = __float2bfloat16_rn(v.y); float l1 = v.y - __bfloat162float(h1);
    __nv_bfloat16 h2 = __float2bfloat16_rn(v.z); float l2 = v.z - __bfloat162float(h2);
    __nv_bfloat16 h3 = __float2bfloat16_rn(v.w); float l3 = v.w - __bfloat162float(h3);
    hi = make_uint2(pk(h0, h1), pk(h2, h3));
    lo = make_uint2(pk(__float2bfloat16_rn(l0), __float2bfloat16_rn(l1)),
                    pk(__float2bfloat16_rn(l2), __float2bfloat16_rn(l3)));
}

__device__ __forceinline__ void mma16816(float* c, const uint32_t* a, const uint32_t* b) {
    asm volatile(
        "mma.sync.aligned.m16n8k16.row.col.f32.bf16.bf16.f32 "
        "{%0,%1,%2,%3}, {%4,%5,%6,%7}, {%8,%9}, {%0,%1,%2,%3};"
        : "+f"(c[0]), "+f"(c[1]), "+f"(c[2]), "+f"(c[3])
        : "r"(a[0]), "r"(a[1]), "r"(a[2]), "r"(a[3]), "r"(b[0]), "r"(b[1]));
}

__device__ __forceinline__ void ldm_x4(uint32_t& r0, uint32_t& r1, uint32_t& r2,
                                       uint32_t& r3, uint32_t saddr) {
    asm volatile("ldmatrix.sync.aligned.m8n8.x4.shared.b16 {%0,%1,%2,%3}, [%4];"
                 : "=r"(r0), "=r"(r1), "=r"(r2), "=r"(r3) : "r"(saddr));
}

// One term: acc[2][4][4] += A-tile(m0..m0+31) x B-tile(n0..n0+31)^T
__device__ __forceinline__ void compute_term(
    uint32_t Abase, uint32_t Bbase, uint32_t laneoff, int m0, int n0,
    float acc[2][4][4])
{
    uint32_t a0 = Abase + (uint32_t)m0 * 272u + laneoff;
    uint32_t a1 = a0 + 16u * 272u;
    uint32_t b0 = Bbase + (uint32_t)n0 * 272u + laneoff;
#pragma unroll
    for (int k0 = 0; k0 < 8; k0++) {
        const uint32_t koff = (uint32_t)k0 * 32u;
        uint32_t a[2][4];
        ldm_x4(a[0][0], a[0][1], a[0][2], a[0][3], a0 + koff);
        ldm_x4(a[1][0], a[1][1], a[1][2], a[1][3], a1 + koff);
#pragma unroll
        for (int p = 0; p < 2; p++) {
            uint32_t b0e, b0o, b1e, b1o;
            ldm_x4(b0e, b0o, b1e, b1o, b0 + (uint32_t)p * (16u * 272u) + koff);
            uint32_t be[2] = { b0e, b1e };
            uint32_t bo[2] = { b0o, b1o };
            mma16816(acc[0][2 * p],     a[0], be);
            mma16816(acc[0][2 * p + 1], a[0], bo);
            mma16816(acc[1][2 * p],     a[1], be);
            mma16816(acc[1][2 * p + 1], a[1], bo);
        }
    }
}

// Stage with 512 threads: quarter 0/1 = A row cols 0-63 / 64-127,
// quarter 2/3 = M row cols 0-63 / 64-127. hi+lo both written.
__device__ __forceinline__ void stage_tiles(
    char* smem, const int* rows, const float* __restrict__ Asrc_base,
    size_t Astride, const float* __restrict__ M, int tid)
{
    const int quarter = tid >> 7;
    const int row     = tid & 127;
    const int c0      = (quarter & 1) * 16;      // float4 offset
    const int isM     = quarter >> 1;
    const uint32_t rb = (uint32_t)row * (RSTRIDE * 2);
    const float* src;
    char *dhi, *dlo;
    if (!isM) {
        int r = rows[row];
        src = (r < 0) ? nullptr : (Asrc_base + (size_t)r * Astride);
        dhi = smem + SM_AHI; dlo = smem + SM_ALO;
    } else {
        src = M + (size_t)row * FF;
        dhi = smem + SM_MHI; dlo = smem + SM_MLO;
    }
#pragma unroll
    for (int c4 = 0; c4 < 16; c4++) {
        float4 v = src ? *(const float4*)(src + (c0 + c4) * 4)
                       : make_float4(0.f, 0.f, 0.f, 0.f);
        uint2 hi, lo;
        split4(v, hi, lo);
        *(uint2*)(dhi + rb + (c0 + c4) * 8) = hi;
        *(uint2*)(dlo + rb + (c0 + c4) * 8) = lo;
    }
}

// ---------------------------------------------------------------------------
// Node projection GEMM: writes g_node_p[r, :].
// ---------------------------------------------------------------------------
__global__ __launch_bounds__(512, 1) void k_gemm_node(
    const float* __restrict__ feature, const float* __restrict__ node_proj)
{
    extern __shared__ char smem[];
    const int t = blockIdx.y;
    const int cnt = g_counts[t];
    const int start = blockIdx.x * 128;
    if (start >= cnt) return;

    const int tid = threadIdx.x, wid = tid >> 5, lane = tid & 31;
    int* rows = (int*)(smem + SM_ROWS);
    if (tid < 128) {
        int idx = start + tid;
        rows[tid] = (idx < cnt) ? g_lists[t][idx] : -1;
    }
    __syncthreads();

    stage_tiles(smem, rows, feature, FF, node_proj + (size_t)t * FF * FF, tid);
    __syncthreads();

    const int m0 = (wid >> 2) * 32, n0 = (wid & 3) * 32;
    const int fr = lane >> 2, fc = lane & 3;
    const uint32_t laneoff = (uint32_t)(lane & 15) * 272u + (uint32_t)(lane >> 4) * 16u;
    uint32_t sb = (uint32_t)(uint64_t)__cvta_generic_to_shared(smem);

    float acc[2][4][4];
#pragma unroll
    for (int mt = 0; mt < 2; mt++)
#pragma unroll
        for (int nt = 0; nt < 4; nt++)
#pragma unroll
            for (int q = 0; q < 4; q++) acc[mt][nt][q] = 0.f;

    compute_term(sb + SM_AHI, sb + SM_MHI, laneoff, m0, n0, acc);
    compute_term(sb + SM_ALO, sb + SM_MHI, laneoff, m0, n0, acc);
    compute_term(sb + SM_AHI, sb + SM_MLO, laneoff, m0, n0, acc);

#pragma unroll
    for (int mt = 0; mt < 2; mt++) {
#pragma unroll
        for (int half = 0; half < 2; half++) {
            int r = rows[m0 + mt * 16 + half * 8 + fr];
            if (r < 0) continue;
            float* dst = g_node_p + (size_t)r * FF;
#pragma unroll
            for (int nt = 0; nt < 4; nt++)
                *(float2*)(dst + n0 + nt * 8 + fc * 2) =
                    make_float2(acc[mt][nt][half * 2], acc[mt][nt][half * 2 + 1]);
        }
    }
}

// ---------------------------------------------------------------------------
// Edge projection GEMM + fused score/softmax epilogue.
// Warp (wm, wn): rows m0..m0+31, cols n0..n0+31 = heads wn*2, wn*2+1.
// ---------------------------------------------------------------------------
__global__ __launch_bounds__(512, 1) void k_gemm_edge(
    const float* __restrict__ edge_fea, const float* __restrict__ edge_proj,
    float* __restrict__ out)
{
    extern __shared__ char smem[];
    const int t = blockIdx.y;
    const int j = blockIdx.z;
    const int cnt = g_counts[t];
    const int start = blockIdx.x * 128;
    if (start >= cnt) return;

    const int tid = threadIdx.x, wid = tid >> 5, lane = tid & 31;
    int* rows = (int*)(smem + SM_ROWS);
    float* ss = (float*)(smem + SM_SCORE);   // [128][8]
    if (tid < 128) {
        int idx = start + tid;
        rows[tid] = (idx < cnt) ? g_lists[t][idx] : -1;
    }
    __syncthreads();

    stage_tiles(smem, rows, edge_fea + j * FF, (size_t)TT * FF,
                edge_proj + ((size_t)t * TT + j) * FF * FF, tid);
    __syncthreads();

    const int m0 = (wid >> 2) * 32, n0 = (wid & 3) * 32;
    const int fr = lane >> 2, fc = lane & 3;
    const uint32_t laneoff = (uint32_t)(lane & 15) * 272u + (uint32_t)(lane >> 4) * 16u;
    uint32_t sb = (uint32_t)(uint64_t)__cvta_generic_to_shared(smem);

    float acc[2][4][4];
#pragma unroll
    for (int mt = 0; mt < 2; mt++)
#pragma unroll
        for (int nt = 0; nt < 4; nt++)
#pragma unroll
            for (int q = 0; q < 4; q++) acc[mt][nt][q] = 0.f;

    compute_term(sb + SM_AHI, sb + SM_MHI, laneoff, m0, n0, acc);
    compute_term(sb + SM_ALO, sb + SM_MHI, laneoff, m0, n0, acc);
    compute_term(sb + SM_AHI, sb + SM_MLO, laneoff, m0, n0, acc);
    __syncthreads();   // tiles free; reuse as node_p floats

    // ---- stage node_p rows: nf[128][132] floats at offset 0 ----
    float* nf = (float*)smem;
#pragma unroll
    for (int s = 0; s < 8; s++) {
        int idx = tid + s * 512;          // float4 slot 0..4095
        int row = idx >> 5, q = idx & 31;
        int r = rows[row];
        float4 v = (r >= 0) ? *(const float4*)(g_node_p + (size_t)r * FF + q * 4)
                            : make_float4(0.f, 0.f, 0.f, 0.f);
        *(float4*)(nf + row * 132 + q * 4) = v;
    }
    __syncthreads();

    // ---- fused score: dot D-fragment cols vs node_p; 2 heads per warp ----
    const int hbase = (wid & 3) * 2;
#pragma unroll
    for (int mt = 0; mt < 2; mt++) {
#pragma unroll
        for (int half = 0; half < 2; half++) {
            const int mrow = m0 + mt * 16 + half * 8 + fr;
            const float* nrow = nf + mrow * 132;
#pragma unroll
            for (int hh = 0; hh < 2; hh++) {
                float p = 0.f;
#pragma unroll
                for (int nt2 = 0; nt2 < 2; nt2++) {
                    const int nt = hh * 2 + nt2;
                    const int c = n0 + nt * 8 + fc * 2;
                    p += acc[mt][nt][half * 2]     * nrow[c]
                       + acc[mt][nt][half * 2 + 1] * nrow[c + 1];
                }
                p += __shfl_xor_sync(0xffffffffu, p, 1);
                p += __shfl_xor_sync(0xffffffffu, p, 2);
                if (fc == 0) ss[mrow * 8 + hbase + hh] = p * 0.25f;
            }
        }
    }
    __syncthreads();

    // ---- softmax over 8 heads, write out[r, j, :] ----
    if (tid < 128) {
        int r = rows[tid];
        if (r >= 0) {
            float v[HH];
            float m = -1e30f;
#pragma unroll
            for (int h = 0; h < HH; h++) { v[h] = ss[tid * 8 + h]; m = fmaxf(m, v[h]); }
            float sum = 0.f;
#pragma unroll
            for (int h = 0; h < HH; h++) { v[h] = expf(v[h] - m); sum += v[h]; }
            float inv = 1.f / sum;
            float* dst = out + (size_t)r * (TT * HH) + j * HH;
#pragma unroll
            for (int h = 0; h < HH; h += 4)
                *(float4*)(dst + h) = make_float4(v[h] * inv, v[h + 1] * inv,
                                                  v[h + 2] * inv, v[h + 3] * inv);
        }
    }
}

// ---------------------------------------------------------------------------
extern "C" void kernel_launch(void* const* d_in, const int* in_sizes, int n_in,
                              void* d_out, int out_size) {
    const float* feature   = (const float*)d_in[0];
    const float* edge_fea  = (const float*)d_in[1];
    const int*   mask      = (const int*)d_in[2];
    const float* node_proj = (const float*)d_in[3];
    const float* edge_proj = (const float*)d_in[4];
    float* out = (float*)d_out;

    const int n = in_sizes[2];

    static int smem_set = 0;
    if (!smem_set) {
        cudaFuncSetAttribute(k_gemm_node, cudaFuncAttributeMaxDynamicSharedMemorySize, SMEM_BYTES);
        cudaFuncSetAttribute(k_gemm_edge, cudaFuncAttributeMaxDynamicSharedMemorySize, SMEM_BYTES);
        smem_set = 1;
    }

    k_zero<<<1, 32>>>();
    k_scatter<<<(n + 255) / 256, 256>>>(mask, n);

    dim3 gn((n + 127) / 128, TT);
    k_gemm_node<<<gn, 512, SMEM_BYTES>>>(feature, node_proj);

    dim3 ge((n + 127) / 128, TT, TT);
    k_gemm_edge<<<ge, 512, SMEM_BYTES>>>(edge_fea, edge_proj, out);
}

// round 12
// speedup vs baseline: 1.1599x; 1.1599x over previous
#include <cuda_runtime.h>
#include <cuda_bf16.h>
#include <cstdint>

#define NN 30000
#define TT 4
#define FF 128
#define HH 8
#define DD 16

// Scratch (no cudaMalloc allowed)
__device__ int   g_lists[TT][NN];
__device__ int   g_counts[TT];
// Pre-converted projection matrices: [t][jj 0-3=edge,4=node][hi=0/lo=1],
// padded tile layout 128 rows x 272 B (136 bf16), flat as uint4[2176].
__device__ uint4 g_prep[TT][5][2][2176];

// ---------------------------------------------------------------------------
__global__ void k_zero() { if (threadIdx.x < TT) g_counts[threadIdx.x] = 0; }

__global__ void k_scatter(const int* __restrict__ mask, int n) {
    int i = blockIdx.x * blockDim.x + threadIdx.x;
    if (i < n) {
        int t = mask[i];
        int p = atomicAdd(&g_counts[t], 1);
        g_lists[t][p] = i;
    }
}

// ---------------------------------------------------------------------------
#define RSTRIDE 136
#define TILE_BYTES (128 * RSTRIDE * 2)    // 34816
#define SM_AHI 0
#define SM_ALO TILE_BYTES
#define SM_MHI (2 * TILE_BYTES)
#define SM_MLO (3 * TILE_BYTES)
#define SM_NF  (4 * TILE_BYTES)           // 128 x 132 floats = 67584
#define SM_ROWS (SM_NF + 67584)           // 128 ints
#define SM_SS   (SM_ROWS + 512)           // 128 x 8 floats
#define SMEM_BYTES (SM_SS + 4096)         // 211456

__device__ __forceinline__ uint32_t pk(__nv_bfloat16 a, __nv_bfloat16 b) {
    __nv_bfloat162 t(a, b);
    return *(uint32_t*)&t;
}

__device__ __forceinline__ void split4(float4 v, uint2& hi, uint2& lo) {
    __nv_bfloat16 h0 = __float2bfloat16_rn(v.x); float l0 = v.x - __bfloat162float(h0);
    __nv_bfloat16 h1 = __float2bfloat16_rn(v.y); float l1 = v.y - __bfloat162float(h1);
    __nv_bfloat16 h2 = __float2bfloat16_rn(v.z); float l2 = v.z - __bfloat162float(h2);
    __nv_bfloat16 h3 = __float2bfloat16_rn(v.w); float l3 = v.w - __bfloat162float(h3);
    hi = make_uint2(pk(h0, h1), pk(h2, h3));
    lo = make_uint2(pk(__float2bfloat16_rn(l0), __float2bfloat16_rn(l1)),
                    pk(__float2bfloat16_rn(l2), __float2bfloat16_rn(l3)));
}

__device__ __forceinline__ void mma16816(float* c, const uint32_t* a,
                                         uint32_t b0, uint32_t b1) {
    asm volatile(
        "mma.sync.aligned.m16n8k16.row.col.f32.bf16.bf16.f32 "
        "{%0,%1,%2,%3}, {%4,%5,%6,%7}, {%8,%9}, {%0,%1,%2,%3};"
        : "+f"(c[0]), "+f"(c[1]), "+f"(c[2]), "+f"(c[3])
        : "r"(a[0]), "r"(a[1]), "r"(a[2]), "r"(a[3]), "r"(b0), "r"(b1));
}

__device__ __forceinline__ void ldm_x4(uint32_t* r, uint32_t saddr) {
    asm volatile("ldmatrix.sync.aligned.m8n8.x4.shared.b16 {%0,%1,%2,%3}, [%4];"
                 : "=r"(r[0]), "=r"(r[1]), "=r"(r[2]), "=r"(r[3]) : "r"(saddr));
}

// ---------------------------------------------------------------------------
// Pre-convert all 20 projection matrices to padded bf16 hi/lo tiles.
// ---------------------------------------------------------------------------
__global__ void k_prep(const float* __restrict__ node_proj,
                       const float* __restrict__ edge_proj) {
    const int mat = blockIdx.x;          // 0..19
    const int t = mat / 5, jj = mat % 5;
    const float* src = (jj == 4) ? node_proj + (size_t)t * FF * FF
                                 : edge_proj + ((size_t)t * TT + jj) * FF * FF;
    const int tid = threadIdx.x;         // 256
    const int row = tid >> 1;
    const int c0  = (tid & 1) * 16;
    char* dh = (char*)g_prep[t][jj][0];
    char* dl = (char*)g_prep[t][jj][1];
    const float* s = src + (size_t)row * FF;
#pragma unroll
    for (int c4 = 0; c4 < 16; c4++) {
        float4 v = *(const float4*)(s + (c0 + c4) * 4);
        uint2 hi, lo;
        split4(v, hi, lo);
        *(uint2*)(dh + row * 272 + (c0 + c4) * 8) = hi;
        *(uint2*)(dl + row * 272 + (c0 + c4) * 8) = lo;
    }
}

// ---------------------------------------------------------------------------
// Fused GEMM: 256 threads, 8 warps in 4(m) x 2(n); warp tile 32m x 64n.
// Per k-step: 12 ldmatrix (Ah,Al 2 each; Mh,Ml 4 each) feed 48 MMAs
// (terms Ah*Mh + Al*Mh + Ah*Ml).
// ---------------------------------------------------------------------------
__device__ __forceinline__ void compute_fused(
    uint32_t sb, uint32_t laneoff, int m0, int n0, float acc[2][8][4])
{
    const uint32_t aH = sb + SM_AHI + (uint32_t)m0 * 272u + laneoff;
    const uint32_t aL = sb + SM_ALO + (uint32_t)m0 * 272u + laneoff;
    const uint32_t bH = sb + SM_MHI + (uint32_t)n0 * 272u + laneoff;
    const uint32_t bL = sb + SM_MLO + (uint32_t)n0 * 272u + laneoff;
#pragma unroll 1
    for (int k0 = 0; k0 < 8; k0++) {
        const uint32_t koff = (uint32_t)k0 * 32u;
        uint32_t ah[2][4], al[2][4], bh[4][4], bl[4][4];
        ldm_x4(ah[0], aH + koff);
        ldm_x4(ah[1], aH + 16u * 272u + koff);
        ldm_x4(al[0], aL + koff);
        ldm_x4(al[1], aL + 16u * 272u + koff);
#pragma unroll
        for (int p = 0; p < 4; p++) {
            ldm_x4(bh[p], bH + (uint32_t)p * (16u * 272u) + koff);
            ldm_x4(bl[p], bL + (uint32_t)p * (16u * 272u) + koff);
        }
#pragma unroll
        for (int p = 0; p < 4; p++) {
#pragma unroll
            for (int mt = 0; mt < 2; mt++) {
                mma16816(acc[mt][2 * p],     ah[mt], bh[p][0], bh[p][2]);
                mma16816(acc[mt][2 * p + 1], ah[mt], bh[p][1], bh[p][3]);
                mma16816(acc[mt][2 * p],     al[mt], bh[p][0], bh[p][2]);
                mma16816(acc[mt][2 * p + 1], al[mt], bh[p][1], bh[p][3]);
                mma16816(acc[mt][2 * p],     ah[mt], bl[p][0], bl[p][2]);
                mma16816(acc[mt][2 * p + 1], ah[mt], bl[p][1], bl[p][3]);
            }
        }
    }
}

__device__ __forceinline__ void stage_A(
    char* smem, const int* rows, const float* __restrict__ base,
    size_t stride, int tid)
{
    const int row = tid >> 1;
    const int c0  = (tid & 1) * 16;
    const int r = rows[row];
    const float* src = (r < 0) ? nullptr : base + (size_t)r * stride;
    const uint32_t rb = (uint32_t)row * 272u;
#pragma unroll
    for (int c4 = 0; c4 < 16; c4++) {
        float4 v = src ? *(const float4*)(src + (c0 + c4) * 4)
                       : make_float4(0.f, 0.f, 0.f, 0.f);
        uint2 hi, lo;
        split4(v, hi, lo);
        *(uint2*)(smem + SM_AHI + rb + (c0 + c4) * 8) = hi;
        *(uint2*)(smem + SM_ALO + rb + (c0 + c4) * 8) = lo;
    }
}

__device__ __forceinline__ void stage_M(char* smem, int t, int jj, int tid) {
    const uint4* sh = g_prep[t][jj][0];
    const uint4* sl = g_prep[t][jj][1];
    uint4* dh = (uint4*)(smem + SM_MHI);
    uint4* dl = (uint4*)(smem + SM_MLO);
#pragma unroll 1
    for (int i = tid; i < 2176; i += 256) {
        dh[i] = sh[i];
        dl[i] = sl[i];
    }
}

__global__ __launch_bounds__(256, 1) void k_fused(
    const float* __restrict__ feature,    // [N,F]
    const float* __restrict__ edge_fea,   // [N,T,F]
    float* __restrict__ out)              // [N,T,H]
{
    extern __shared__ char smem[];
    const int t = blockIdx.y;
    const int cnt = g_counts[t];
    const int start = blockIdx.x * 128;
    if (start >= cnt) return;

    const int tid = threadIdx.x, wid = tid >> 5, lane = tid & 31;
    int*   rows = (int*)(smem + SM_ROWS);
    float* nf   = (float*)(smem + SM_NF);     // [128][132]
    float* ss   = (float*)(smem + SM_SS);     // [128][8]

    if (tid < 128) {
        int idx = start + tid;
        rows[tid] = (idx < cnt) ? g_lists[t][idx] : -1;
    }
    __syncthreads();

    const int m0 = (wid >> 1) * 32;           // 4 m-warps
    const int n0 = (wid & 1) * 64;            // 2 n-warps
    const int fr = lane >> 2, fc = lane & 3;
    const uint32_t laneoff = (uint32_t)(lane & 15) * 272u + (uint32_t)(lane >> 4) * 16u;
    const uint32_t sb = (uint32_t)(uint64_t)__cvta_generic_to_shared(smem);

    float acc[2][8][4];

    // ================= node phase: nf = feature @ node_proj^T =================
    stage_A(smem, rows, feature, FF, tid);
    stage_M(smem, t, 4, tid);
    __syncthreads();

#pragma unroll
    for (int mt = 0; mt < 2; mt++)
#pragma unroll
        for (int nt = 0; nt < 8; nt++)
#pragma unroll
            for (int q = 0; q < 4; q++) acc[mt][nt][q] = 0.f;
    compute_fused(sb, laneoff, m0, n0, acc);

#pragma unroll
    for (int mt = 0; mt < 2; mt++)
#pragma unroll
        for (int half = 0; half < 2; half++) {
            const int mrow = m0 + mt * 16 + half * 8 + fr;
            float* drow = nf + mrow * 132;
#pragma unroll
            for (int nt = 0; nt < 8; nt++)
                *(float2*)(drow + n0 + nt * 8 + fc * 2) =
                    make_float2(acc[mt][nt][half * 2], acc[mt][nt][half * 2 + 1]);
        }
    __syncthreads();

    // ================= edge phases: j = 0..3 =================
    for (int j = 0; j < TT; j++) {
        stage_A(smem, rows, edge_fea + j * FF, (size_t)TT * FF, tid);
        stage_M(smem, t, j, tid);
        __syncthreads();

#pragma unroll
        for (int mt = 0; mt < 2; mt++)
#pragma unroll
            for (int nt = 0; nt < 8; nt++)
#pragma unroll
                for (int q = 0; q < 4; q++) acc[mt][nt][q] = 0.f;
        compute_fused(sb, laneoff, m0, n0, acc);

        // fused score: dot acc fragments against nf; warp covers heads
        // hbase..hbase+3 (n0..n0+63 = 4 heads of 16 cols each)
        const int hbase = (wid & 1) * 4;
#pragma unroll
        for (int mt = 0; mt < 2; mt++) {
#pragma unroll
            for (int half = 0; half < 2; half++) {
                const int mrow = m0 + mt * 16 + half * 8 + fr;
                const float* nrow = nf + mrow * 132;
#pragma unroll
                for (int hh = 0; hh < 4; hh++) {
                    float p = 0.f;
#pragma unroll
                    for (int nt2 = 0; nt2 < 2; nt2++) {
                        const int nt = hh * 2 + nt2;
                        const int c = n0 + nt * 8 + fc * 2;
                        p += acc[mt][nt][half * 2]     * nrow[c]
                           + acc[mt][nt][half * 2 + 1] * nrow[c + 1];
                    }
                    p += __shfl_xor_sync(0xffffffffu, p, 1);
                    p += __shfl_xor_sync(0xffffffffu, p, 2);
                    if (fc == 0) ss[mrow * 8 + hbase + hh] = p * 0.25f;
                }
            }
        }
        __syncthreads();

        // softmax over 8 heads, write out[r, j, :]
        if (tid < 128) {
            int r = rows[tid];
            if (r >= 0) {
                float v[HH];
                float m = -1e30f;
#pragma unroll
                for (int h = 0; h < HH; h++) { v[h] = ss[tid * 8 + h]; m = fmaxf(m, v[h]); }
                float sum = 0.f;
#pragma unroll
                for (int h = 0; h < HH; h++) { v[h] = expf(v[h] - m); sum += v[h]; }
                float inv = 1.f / sum;
                float* dst = out + (size_t)r * (TT * HH) + j * HH;
#pragma unroll
                for (int h = 0; h < HH; h += 4)
                    *(float4*)(dst + h) = make_float4(v[h] * inv, v[h + 1] * inv,
                                                      v[h + 2] * inv, v[h + 3] * inv);
            }
        }
        // next iteration's stage_A/stage_M write only the bf16 tiles (disjoint
        // from ss/nf); the __syncthreads after staging orders everything.
    }
}

// ---------------------------------------------------------------------------
extern "C" void kernel_launch(void* const* d_in, const int* in_sizes, int n_in,
                              void* d_out, int out_size) {
    const float* feature   = (const float*)d_in[0];
    const float* edge_fea  = (const float*)d_in[1];
    const int*   mask      = (const int*)d_in[2];
    const float* node_proj = (const float*)d_in[3];
    const float* edge_proj = (const float*)d_in[4];
    float* out = (float*)d_out;

    const int n = in_sizes[2];

    static int smem_set = 0;
    if (!smem_set) {
        cudaFuncSetAttribute(k_fused, cudaFuncAttributeMaxDynamicSharedMemorySize, SMEM_BYTES);
        smem_set = 1;
    }

    k_zero<<<1, 32>>>();
    k_scatter<<<(n + 255) / 256, 256>>>(mask, n);
    k_prep<<<20, 256>>>(node_proj, edge_proj);

    dim3 g((n + 127) / 128, TT);
    k_fused<<<g, 256, SMEM_BYTES>>>(feature, edge_fea, out);
}

// round 15
// speedup vs baseline: 1.3148x; 1.1335x over previous
#include <cuda_runtime.h>
#include <cuda_bf16.h>
#include <cstdint>

#define NN 30000
#define TT 4
#define FF 128
#define HH 8

#define ROWS_J 64              // rows per job
#define NCH 128                // max chunks per type (64*128=8192 >= cnt[t])
#define NJOBS (TT * NCH)       // 512 job slots

// Scratch (no cudaMalloc allowed)
__device__ int   g_lists[TT][NN];
__device__ int   g_counts[TT];
__device__ int   g_job;
// Pre-converted projection matrices: [t][jj 0-3=edge,4=node][hi/lo],
// 128 rows x 272 B padded tiles, flat as uint4[2176].
__device__ uint4 g_prep[TT][5][2][2176];

// ---------------------------------------------------------------------------
__global__ void k_zero() {
    if (threadIdx.x < TT) g_counts[threadIdx.x] = 0;
    if (threadIdx.x == 0) g_job = 0;
}

__global__ void k_scatter(const int* __restrict__ mask, int n) {
    int i = blockIdx.x * blockDim.x + threadIdx.x;
    if (i < n) {
        int t = mask[i];
        int p = atomicAdd(&g_counts[t], 1);
        g_lists[t][p] = i;
    }
}

// ---------------------------------------------------------------------------
// SMEM layout (64-row A tiles, 128-row M tiles)
// ---------------------------------------------------------------------------
#define SM_AHI 0                           // 64*272 = 17408
#define SM_ALO 17408
#define SM_MHI 34816                       // 128*272 = 34816
#define SM_MLO 69632
#define SM_NF  104448                      // 64*132*4 = 33792
#define SM_ROWS 138240                     // 64 ints
#define SM_SS   138496                     // 64*8 floats = 2048
#define SMEM_BYTES 140800

__device__ __forceinline__ uint32_t pk(__nv_bfloat16 a, __nv_bfloat16 b) {
    __nv_bfloat162 t(a, b);
    return *(uint32_t*)&t;
}

__device__ __forceinline__ void split4(float4 v, uint2& hi, uint2& lo) {
    __nv_bfloat16 h0 = __float2bfloat16_rn(v.x); float l0 = v.x - __bfloat162float(h0);
    __nv_bfloat16 h1 = __float2bfloat16_rn(v.y); float l1 = v.y - __bfloat162float(h1);
    __nv_bfloat16 h2 = __float2bfloat16_rn(v.z); float l2 = v.z - __bfloat162float(h2);
    __nv_bfloat16 h3 = __float2bfloat16_rn(v.w); float l3 = v.w - __bfloat162float(h3);
    hi = make_uint2(pk(h0, h1), pk(h2, h3));
    lo = make_uint2(pk(__float2bfloat16_rn(l0), __float2bfloat16_rn(l1)),
                    pk(__float2bfloat16_rn(l2), __float2bfloat16_rn(l3)));
}

__device__ __forceinline__ void mma16816(float* c, const uint32_t* a,
                                         uint32_t b0, uint32_t b1) {
    asm volatile(
        "mma.sync.aligned.m16n8k16.row.col.f32.bf16.bf16.f32 "
        "{%0,%1,%2,%3}, {%4,%5,%6,%7}, {%8,%9}, {%0,%1,%2,%3};"
        : "+f"(c[0]), "+f"(c[1]), "+f"(c[2]), "+f"(c[3])
        : "r"(a[0]), "r"(a[1]), "r"(a[2]), "r"(a[3]), "r"(b0), "r"(b1));
}

__device__ __forceinline__ void ldm_x4(uint32_t* r, uint32_t saddr) {
    asm volatile("ldmatrix.sync.aligned.m8n8.x4.shared.b16 {%0,%1,%2,%3}, [%4];"
                 : "=r"(r[0]), "=r"(r[1]), "=r"(r[2]), "=r"(r[3]) : "r"(saddr));
}

// ---------------------------------------------------------------------------
// Pre-convert all 20 projection matrices to padded bf16 hi/lo tiles.
// ---------------------------------------------------------------------------
__global__ void k_prep(const float* __restrict__ node_proj,
                       const float* __restrict__ edge_proj) {
    const int mat = blockIdx.x;          // 0..19
    const int t = mat / 5, jj = mat % 5;
    const float* src = (jj == 4) ? node_proj + (size_t)t * FF * FF
                                 : edge_proj + ((size_t)t * TT + jj) * FF * FF;
    const int tid = threadIdx.x;         // 256
    const int row = tid >> 1;
    const int c0  = (tid & 1) * 16;
    char* dh = (char*)g_prep[t][jj][0];
    char* dl = (char*)g_prep[t][jj][1];
    const float* s = src + (size_t)row * FF;
#pragma unroll
    for (int c4 = 0; c4 < 16; c4++) {
        float4 v = *(const float4*)(s + (c0 + c4) * 4);
        uint2 hi, lo;
        split4(v, hi, lo);
        *(uint2*)(dh + row * 272 + (c0 + c4) * 8) = hi;
        *(uint2*)(dl + row * 272 + (c0 + c4) * 8) = lo;
    }
}

// ---------------------------------------------------------------------------
// Fused core pieces (16 warps, warp tile 16m x 32n, acc[4][4]).
// 3-term: Ah*Mh + Al*Mh + Ah*Ml.
// ---------------------------------------------------------------------------
__device__ __forceinline__ void compute_fused(
    uint32_t sb, uint32_t laneoff, int m0, int n0, float acc[4][4])
{
    const uint32_t aH = sb + SM_AHI + (uint32_t)m0 * 272u + laneoff;
    const uint32_t aL = sb + SM_ALO + (uint32_t)m0 * 272u + laneoff;
    const uint32_t bH = sb + SM_MHI + (uint32_t)n0 * 272u + laneoff;
    const uint32_t bL = sb + SM_MLO + (uint32_t)n0 * 272u + laneoff;
#pragma unroll 1
    for (int k0 = 0; k0 < 8; k0++) {
        const uint32_t koff = (uint32_t)k0 * 32u;
        uint32_t ah[4], al[4], bh[2][4], bl[2][4];
        ldm_x4(ah, aH + koff);
        ldm_x4(al, aL + koff);
#pragma unroll
        for (int p = 0; p < 2; p++) {
            ldm_x4(bh[p], bH + (uint32_t)p * (16u * 272u) + koff);
            ldm_x4(bl[p], bL + (uint32_t)p * (16u * 272u) + koff);
        }
#pragma unroll
        for (int p = 0; p < 2; p++) {
            mma16816(acc[2 * p],     ah, bh[p][0], bh[p][2]);
            mma16816(acc[2 * p + 1], ah, bh[p][1], bh[p][3]);
            mma16816(acc[2 * p],     al, bh[p][0], bh[p][2]);
            mma16816(acc[2 * p + 1], al, bh[p][1], bh[p][3]);
            mma16816(acc[2 * p],     ah, bl[p][0], bl[p][2]);
            mma16816(acc[2 * p + 1], ah, bl[p][1], bl[p][3]);
        }
    }
}

// stage A: 64 rows x 128 cols, hi+lo. 8 threads per row, 4 float4 each.
__device__ __forceinline__ void stage_A(
    char* smem, const int* rows, const float* __restrict__ base,
    size_t stride, int tid)
{
    const int row = tid >> 3;            // 0..63
    const int c0  = (tid & 7) * 4;       // float4 index base
    const int r = rows[row];
    const float* src = (r < 0) ? nullptr : base + (size_t)r * stride;
    const uint32_t rb = (uint32_t)row * 272u;
#pragma unroll
    for (int c4 = 0; c4 < 4; c4++) {
        float4 v = src ? *(const float4*)(src + (c0 + c4) * 4)
                       : make_float4(0.f, 0.f, 0.f, 0.f);
        uint2 hi, lo;
        split4(v, hi, lo);
        *(uint2*)(smem + SM_AHI + rb + (c0 + c4) * 8) = hi;
        *(uint2*)(smem + SM_ALO + rb + (c0 + c4) * 8) = lo;
    }
}

__device__ __forceinline__ void stage_M(char* smem, int t, int jj, int tid) {
    const uint4* sh = g_prep[t][jj][0];
    const uint4* sl = g_prep[t][jj][1];
    uint4* dh = (uint4*)(smem + SM_MHI);
    uint4* dl = (uint4*)(smem + SM_MLO);
#pragma unroll 1
    for (int i = tid; i < 2176; i += 512) {
        dh[i] = sh[i];
        dl[i] = sl[i];
    }
}

// ---------------------------------------------------------------------------
// Persistent fused kernel: 152 CTAs steal (t, chunk64) jobs dynamically.
// Per job: node phase -> nf (SMEM), then 4 edge phases each ending in a
// fused score + softmax-over-heads epilogue writing out[r, j, :].
// ---------------------------------------------------------------------------
__global__ __launch_bounds__(512, 1) void k_fused(
    const float* __restrict__ feature,    // [N,F]
    const float* __restrict__ edge_fea,   // [N,T,F]
    float* __restrict__ out)              // [N,T,H]
{
    extern __shared__ char smem[];
    const int tid = threadIdx.x, wid = tid >> 5, lane = tid & 31;
    int*   rows = (int*)(smem + SM_ROWS);
    float* nf   = (float*)(smem + SM_NF);     // [64][132]
    float* ss   = (float*)(smem + SM_SS);     // [64][8]
    int*   jobp = (int*)(smem + SM_SS + 2048);

    const int m0 = (wid >> 2) * 16;           // 4 m-warps x 16 rows
    const int n0 = (wid & 3) * 32;            // 4 n-warps x 32 cols
    const int fr = lane >> 2, fc = lane & 3;
    const uint32_t laneoff = (uint32_t)(lane & 15) * 272u + (uint32_t)(lane >> 4) * 16u;
    const uint32_t sb = (uint32_t)(uint64_t)__cvta_generic_to_shared(smem);

    for (;;) {
        __syncthreads();                      // protects jobp + smem reuse
        if (tid == 0) *jobp = atomicAdd(&g_job, 1);
        __syncthreads();
        const int job = *jobp;
        if (job >= NJOBS) break;              // uniform exit

        const int t = job & 3;
        const int chunk = job >> 2;
        const int cnt = g_counts[t];
        const int start = chunk * ROWS_J;
        if (start >= cnt) continue;           // empty job (uniform)

        if (tid < ROWS_J) {
            int idx = start + tid;
            rows[tid] = (idx < cnt) ? g_lists[t][idx] : -1;
        }
        __syncthreads();

        float acc[4][4];

        // ---------- node phase: nf = feature @ node_proj^T ----------
        stage_A(smem, rows, feature, FF, tid);
        stage_M(smem, t, 4, tid);
        __syncthreads();
#pragma unroll
        for (int nt = 0; nt < 4; nt++)
#pragma unroll
            for (int q = 0; q < 4; q++) acc[nt][q] = 0.f;
        compute_fused(sb, laneoff, m0, n0, acc);

#pragma unroll
        for (int half = 0; half < 2; half++) {
            const int mrow = m0 + half * 8 + fr;
            float* drow = nf + mrow * 132;
#pragma unroll
            for (int nt = 0; nt < 4; nt++)
                *(float2*)(drow + n0 + nt * 8 + fc * 2) =
                    make_float2(acc[nt][half * 2], acc[nt][half * 2 + 1]);
        }
        __syncthreads();

        // ---------- edge phases: j = 0..3 ----------
        for (int j = 0; j < TT; j++) {
            stage_A(smem, rows, edge_fea + j * FF, (size_t)TT * FF, tid);
            stage_M(smem, t, j, tid);
            __syncthreads();
#pragma unroll
            for (int nt = 0; nt < 4; nt++)
#pragma unroll
                for (int q = 0; q < 4; q++) acc[nt][q] = 0.f;
            compute_fused(sb, laneoff, m0, n0, acc);

            // fused score: warp covers heads hbase, hbase+1
            const int hbase = (wid & 3) * 2;
#pragma unroll
            for (int half = 0; half < 2; half++) {
                const int mrow = m0 + half * 8 + fr;
                const float* nrow = nf + mrow * 132;
#pragma unroll
                for (int hh = 0; hh < 2; hh++) {
                    float p = 0.f;
#pragma unroll
                    for (int nt2 = 0; nt2 < 2; nt2++) {
                        const int nt = hh * 2 + nt2;
                        const int c = n0 + nt * 8 + fc * 2;
                        p += acc[nt][half * 2]     * nrow[c]
                           + acc[nt][half * 2 + 1] * nrow[c + 1];
                    }
                    p += __shfl_xor_sync(0xffffffffu, p, 1);
                    p += __shfl_xor_sync(0xffffffffu, p, 2);
                    if (fc == 0) ss[mrow * 8 + hbase + hh] = p * 0.25f;
                }
            }
            __syncthreads();

            // softmax over 8 heads, write out[r, j, :]
            if (tid < ROWS_J) {
                int r = rows[tid];
                if (r >= 0) {
                    float v[HH];
                    float m = -1e30f;
#pragma unroll
                    for (int h = 0; h < HH; h++) { v[h] = ss[tid * 8 + h]; m = fmaxf(m, v[h]); }
                    float sum = 0.f;
#pragma unroll
                    for (int h = 0; h < HH; h++) { v[h] = expf(v[h] - m); sum += v[h]; }
                    float inv = 1.f / sum;
                    float* dst = out + (size_t)r * (TT * HH) + j * HH;
#pragma unroll
                    for (int h = 0; h < HH; h += 4)
                        *(float4*)(dst + h) = make_float4(v[h] * inv, v[h + 1] * inv,
                                                          v[h + 2] * inv, v[h + 3] * inv);
                }
            }
            __syncthreads();   // ss/out done before next phase restages
        }
    }
}

// ---------------------------------------------------------------------------
extern "C" void kernel_launch(void* const* d_in, const int* in_sizes, int n_in,
                              void* d_out, int out_size) {
    const float* feature   = (const float*)d_in[0];
    const float* edge_fea  = (const float*)d_in[1];
    const int*   mask      = (const int*)d_in[2];
    const float* node_proj = (const float*)d_in[3];
    const float* edge_proj = (const float*)d_in[4];
    float* out = (float*)d_out;

    const int n = in_sizes[2];

    static int smem_set = 0;
    if (!smem_set) {
        cudaFuncSetAttribute(k_fused, cudaFuncAttributeMaxDynamicSharedMemorySize, SMEM_BYTES);
        smem_set = 1;
    }

    k_zero<<<1, 32>>>();
    k_scatter<<<(n + 255) / 256, 256>>>(mask, n);
    k_prep<<<20, 256>>>(node_proj, edge_proj);

    k_fused<<<152, 512, SMEM_BYTES>>>(feature, edge_fea, out);
}

// round 16
// speedup vs baseline: 1.5596x; 1.1862x over previous
#include <cuda_runtime.h>
#include <cuda_bf16.h>
#include <cstdint>

#define NN 30000
#define TT 4
#define FF 128
#define HH 8

#define ROWS_J 32              // rows per job
#define NCH 256                // chunks per type (32*256 = 8192 >= cnt[t])
#define NJOBS (TT * NCH)       // 1024 job slots

// Scratch (no cudaMalloc allowed)
__device__ int   g_lists[TT][NN];
__device__ int   g_counts[TT];
__device__ int   g_job;
// Pre-converted projection matrices: [t][jj 0-3=edge,4=node][hi/lo],
// 128 rows x 272 B padded tiles, hi then lo contiguous (4352 uint4).
__device__ uint4 g_prep[TT][5][2][2176];

// ---------------------------------------------------------------------------
__global__ void k_zero() {
    if (threadIdx.x < TT) g_counts[threadIdx.x] = 0;
    if (threadIdx.x == 0) g_job = 0;
}

__global__ void k_scatter(const int* __restrict__ mask, int n) {
    int i = blockIdx.x * blockDim.x + threadIdx.x;
    if (i < n) {
        int t = mask[i];
        int p = atomicAdd(&g_counts[t], 1);
        g_lists[t][p] = i;
    }
}

// ---------------------------------------------------------------------------
// SMEM layout: double-buffered A (32x272 hi+lo) and M (128x272 hi+lo).
// ---------------------------------------------------------------------------
#define A_BUF 17408            // per-buffer: hi 8704 + lo 8704
#define M_BUF 69632            // per-buffer: hi 34816 + lo 34816
#define SM_A  0                // 2 buffers: 34816
#define SM_M  34816            // 2 buffers: 139264 -> ends 174080
#define SM_NF 174080           // 32 x 132 floats = 16896 -> 190976
#define SM_ROWS 190976         // 32 ints -> 191104
#define SM_SS 191104           // 32 x 8 floats -> 192128
#define SM_JOB 192128
#define SMEM_BYTES 192160

__device__ __forceinline__ uint32_t pk(__nv_bfloat16 a, __nv_bfloat16 b) {
    __nv_bfloat162 t(a, b);
    return *(uint32_t*)&t;
}

__device__ __forceinline__ void split4(float4 v, uint2& hi, uint2& lo) {
    __nv_bfloat16 h0 = __float2bfloat16_rn(v.x); float l0 = v.x - __bfloat162float(h0);
    __nv_bfloat16 h1 = __float2bfloat16_rn(v.y); float l1 = v.y - __bfloat162float(h1);
    __nv_bfloat16 h2 = __float2bfloat16_rn(v.z); float l2 = v.z - __bfloat162float(h2);
    __nv_bfloat16 h3 = __float2bfloat16_rn(v.w); float l3 = v.w - __bfloat162float(h3);
    hi = make_uint2(pk(h0, h1), pk(h2, h3));
    lo = make_uint2(pk(__float2bfloat16_rn(l0), __float2bfloat16_rn(l1)),
                    pk(__float2bfloat16_rn(l2), __float2bfloat16_rn(l3)));
}

__device__ __forceinline__ void mma16816(float* c, const uint32_t* a,
                                         uint32_t b0, uint32_t b1) {
    asm volatile(
        "mma.sync.aligned.m16n8k16.row.col.f32.bf16.bf16.f32 "
        "{%0,%1,%2,%3}, {%4,%5,%6,%7}, {%8,%9}, {%0,%1,%2,%3};"
        : "+f"(c[0]), "+f"(c[1]), "+f"(c[2]), "+f"(c[3])
        : "r"(a[0]), "r"(a[1]), "r"(a[2]), "r"(a[3]), "r"(b0), "r"(b1));
}

__device__ __forceinline__ void ldm_x4(uint32_t* r, uint32_t saddr) {
    asm volatile("ldmatrix.sync.aligned.m8n8.x4.shared.b16 {%0,%1,%2,%3}, [%4];"
                 : "=r"(r[0]), "=r"(r[1]), "=r"(r[2]), "=r"(r[3]) : "r"(saddr));
}

__device__ __forceinline__ void cpasync16(uint32_t dst, const void* src) {
    asm volatile("cp.async.cg.shared.global [%0], [%1], 16;"
                 :: "r"(dst), "l"(src) : "memory");
}
#define CP_COMMIT() asm volatile("cp.async.commit_group;" ::: "memory")
#define CP_WAIT0()  asm volatile("cp.async.wait_group 0;" ::: "memory")

// ---------------------------------------------------------------------------
// Pre-convert all 20 projection matrices to padded bf16 hi/lo tiles.
// ---------------------------------------------------------------------------
__global__ void k_prep(const float* __restrict__ node_proj,
                       const float* __restrict__ edge_proj) {
    const int mat = blockIdx.x;          // 0..19
    const int t = mat / 5, jj = mat % 5;
    const float* src = (jj == 4) ? node_proj + (size_t)t * FF * FF
                                 : edge_proj + ((size_t)t * TT + jj) * FF * FF;
    const int tid = threadIdx.x;         // 256
    const int row = tid >> 1;
    const int c0  = (tid & 1) * 16;
    char* dh = (char*)g_prep[t][jj][0];
    char* dl = (char*)g_prep[t][jj][1];
    const float* s = src + (size_t)row * FF;
#pragma unroll
    for (int c4 = 0; c4 < 16; c4++) {
        float4 v = *(const float4*)(s + (c0 + c4) * 4);
        uint2 hi, lo;
        split4(v, hi, lo);
        *(uint2*)(dh + row * 272 + (c0 + c4) * 8) = hi;
        *(uint2*)(dl + row * 272 + (c0 + c4) * 8) = lo;
    }
}

// ---------------------------------------------------------------------------
// Staging helpers (512 threads).
// ---------------------------------------------------------------------------
// M copy: 4352 uint4 via cp.async (hi then lo, contiguous in g_prep).
__device__ __forceinline__ void issue_M(uint32_t sb, int buf, int t, int jj, int tid) {
    const uint4* src = g_prep[t][jj][0];
    uint32_t dst = sb + SM_M + buf * M_BUF;
#pragma unroll
    for (int s = 0; s < 8; s++) {
        int i = tid + s * 512;
        cpasync16(dst + i * 16, src + i);
    }
    {
        int i = tid + 4096;
        if (i < 4352) cpasync16(dst + i * 16, src + i);
    }
}

// A load: each thread grabs 2 float4 (row = tid>>4, cols (tid&15)*8 .. +7).
__device__ __forceinline__ void issue_A(float4* v, const int* rows,
                                        const float* __restrict__ base,
                                        size_t stride, int tid) {
    const int row = tid >> 4;
    const int c4 = (tid & 15) * 2;
    const int r = rows[row];
    if (r >= 0) {
        const float* src = base + (size_t)r * stride;
        v[0] = *(const float4*)(src + c4 * 4);
        v[1] = *(const float4*)(src + c4 * 4 + 4);
    } else {
        v[0] = make_float4(0.f, 0.f, 0.f, 0.f);
        v[1] = make_float4(0.f, 0.f, 0.f, 0.f);
    }
}

__device__ __forceinline__ void store_A(char* smem, int buf, const float4* v, int tid) {
    const int row = tid >> 4;
    const int c4 = (tid & 15) * 2;
    char* hb = smem + SM_A + buf * A_BUF;
    char* lb = hb + 8704;
    const uint32_t rb = (uint32_t)row * 272u;
#pragma unroll
    for (int q = 0; q < 2; q++) {
        uint2 hi, lo;
        split4(v[q], hi, lo);
        *(uint2*)(hb + rb + (c4 + q) * 8) = hi;
        *(uint2*)(lb + rb + (c4 + q) * 8) = lo;
    }
}

// ---------------------------------------------------------------------------
// Compute: warp tile 16m x 16n, 3-term. Per k-step: 4 ldmatrix, 6 mma.
// ---------------------------------------------------------------------------
__device__ __forceinline__ void compute16(uint32_t aH, uint32_t aL,
                                          uint32_t bH, uint32_t bL,
                                          float acc[2][4]) {
#pragma unroll 1
    for (int k0 = 0; k0 < 8; k0++) {
        const uint32_t koff = (uint32_t)k0 * 32u;
        uint32_t ah[4], al[4], bh[4], bl[4];
        ldm_x4(ah, aH + koff);
        ldm_x4(al, aL + koff);
        ldm_x4(bh, bH + koff);
        ldm_x4(bl, bL + koff);
        mma16816(acc[0], ah, bh[0], bh[2]);
        mma16816(acc[1], ah, bh[1], bh[3]);
        mma16816(acc[0], al, bh[0], bh[2]);
        mma16816(acc[1], al, bh[1], bh[3]);
        mma16816(acc[0], ah, bl[0], bl[2]);
        mma16816(acc[1], ah, bl[1], bl[3]);
    }
}

// ---------------------------------------------------------------------------
// Persistent fused kernel, 32-row jobs, double-buffered pipelined staging.
// 16 warps: mwid = wid>>3 (2 m-groups x 16 rows), nwid = wid&7 (head).
// ---------------------------------------------------------------------------
__global__ __launch_bounds__(512, 1) void k_fused(
    const float* __restrict__ feature,    // [N,F]
    const float* __restrict__ edge_fea,   // [N,T,F]
    float* __restrict__ out)              // [N,T,H]
{
    extern __shared__ char smem[];
    const int tid = threadIdx.x, wid = tid >> 5, lane = tid & 31;
    int*   rows = (int*)(smem + SM_ROWS);
    float* nf   = (float*)(smem + SM_NF);     // [32][132]
    float* ss   = (float*)(smem + SM_SS);     // [32][8]
    int*   jobp = (int*)(smem + SM_JOB);

    const int m0 = (wid >> 3) * 16;
    const int nwid = wid & 7;                 // head index
    const int n0 = nwid * 16;
    const int fr = lane >> 2, fc = lane & 3;
    const uint32_t laneoff = (uint32_t)(lane & 15) * 272u + (uint32_t)(lane >> 4) * 16u;
    const uint32_t sb = (uint32_t)(uint64_t)__cvta_generic_to_shared(smem);

    for (;;) {
        __syncthreads();                      // smem reuse + jobp
        if (tid == 0) *jobp = atomicAdd(&g_job, 1);
        __syncthreads();
        const int job = *jobp;
        if (job >= NJOBS) break;

        const int t = job & 3;
        const int chunk = job >> 2;
        const int cnt = g_counts[t];
        const int start = chunk * ROWS_J;
        if (start >= cnt) continue;

        if (tid < ROWS_J) {
            int idx = start + tid;
            rows[tid] = (idx < cnt) ? g_lists[t][idx] : -1;
        }
        issue_M(sb, 0, t, 4, tid);            // node matrix into buf 0
        CP_COMMIT();
        __syncthreads();                      // rows visible

        {   // phase-0 A staging (exposed; ~LDG latency only)
            float4 v[2];
            issue_A(v, rows, feature, FF, tid);
            store_A(smem, 0, v, tid);
        }
        CP_WAIT0();
        __syncthreads();

#pragma unroll 1
        for (int ph = 0; ph < 5; ph++) {
            const int cur = ph & 1, nxt = cur ^ 1;
            float4 v[2];
            if (ph < 4) {
                issue_M(sb, nxt, t, ph, tid); // phase ph+1 uses edge j=ph
                CP_COMMIT();
                issue_A(v, rows, edge_fea + ph * FF, (size_t)TT * FF, tid);
            }

            float acc[2][4];
#pragma unroll
            for (int nt = 0; nt < 2; nt++)
#pragma unroll
                for (int q = 0; q < 4; q++) acc[nt][q] = 0.f;
            {
                const uint32_t aH = sb + SM_A + cur * A_BUF + (uint32_t)m0 * 272u + laneoff;
                const uint32_t bH = sb + SM_M + cur * M_BUF + (uint32_t)n0 * 272u + laneoff;
                compute16(aH, aH + 8704u, bH, bH + 34816u, acc);
            }

            if (ph == 0) {
                // node result -> nf
#pragma unroll
                for (int half = 0; half < 2; half++) {
                    const int mrow = m0 + half * 8 + fr;
                    float* drow = nf + mrow * 132;
#pragma unroll
                    for (int nt = 0; nt < 2; nt++)
                        *(float2*)(drow + n0 + nt * 8 + fc * 2) =
                            make_float2(acc[nt][half * 2], acc[nt][half * 2 + 1]);
                }
            } else {
                // fused score for head nwid
#pragma unroll
                for (int half = 0; half < 2; half++) {
                    const int mrow = m0 + half * 8 + fr;
                    const float* nrow = nf + mrow * 132;
                    float p = acc[0][half * 2]     * nrow[n0 + fc * 2]
                            + acc[0][half * 2 + 1] * nrow[n0 + fc * 2 + 1]
                            + acc[1][half * 2]     * nrow[n0 + 8 + fc * 2]
                            + acc[1][half * 2 + 1] * nrow[n0 + 8 + fc * 2 + 1];
                    p += __shfl_xor_sync(0xffffffffu, p, 1);
                    p += __shfl_xor_sync(0xffffffffu, p, 2);
                    if (fc == 0) ss[mrow * 8 + nwid] = p * 0.25f;
                }
            }

            if (ph < 4) store_A(smem, nxt, v, tid);
            __syncthreads();                  // ss / nf / A-stage visible

            if (ph > 0) {
                const int j = ph - 1;
                if (tid < ROWS_J) {
                    int r = rows[tid];
                    if (r >= 0) {
                        float sv[HH];
                        float m = -1e30f;
#pragma unroll
                        for (int h = 0; h < HH; h++) { sv[h] = ss[tid * 8 + h]; m = fmaxf(m, sv[h]); }
                        float sum = 0.f;
#pragma unroll
                        for (int h = 0; h < HH; h++) { sv[h] = expf(sv[h] - m); sum += sv[h]; }
                        float inv = 1.f / sum;
                        float* dst = out + (size_t)r * (TT * HH) + j * HH;
#pragma unroll
                        for (int h = 0; h < HH; h += 4)
                            *(float4*)(dst + h) = make_float4(sv[h] * inv, sv[h + 1] * inv,
                                                              sv[h + 2] * inv, sv[h + 3] * inv);
                    }
                }
            }
            if (ph < 4) CP_WAIT0();
            __syncthreads();                  // ss reusable; M(nxt) visible
        }
    }
}

// ---------------------------------------------------------------------------
extern "C" void kernel_launch(void* const* d_in, const int* in_sizes, int n_in,
                              void* d_out, int out_size) {
    const float* feature   = (const float*)d_in[0];
    const float* edge_fea  = (const float*)d_in[1];
    const int*   mask      = (const int*)d_in[2];
    const float* node_proj = (const float*)d_in[3];
    const float* edge_proj = (const float*)d_in[4];
    float* out = (float*)d_out;

    const int n = in_sizes[2];

    static int smem_set = 0;
    if (!smem_set) {
        cudaFuncSetAttribute(k_fused, cudaFuncAttributeMaxDynamicSharedMemorySize, SMEM_BYTES);
        smem_set = 1;
    }

    k_zero<<<1, 32>>>();
    k_scatter<<<(n + 255) / 256, 256>>>(mask, n);
    k_prep<<<20, 256>>>(node_proj, edge_proj);

    k_fused<<<152, 512, SMEM_BYTES>>>(feature, edge_fea, out);
}

// round 17
// speedup vs baseline: 1.6353x; 1.0486x over previous
#include <cuda_runtime.h>
#include <cuda_bf16.h>
#include <cstdint>

#define NN 30000
#define TT 4
#define FF 128
#define HH 8

#define ROWS_J 32              // rows per job
#define NCH 256                // chunks per type (32*256 = 8192 >= cnt[t])
#define NJOBS (TT * NCH)       // 1024 job slots

// Scratch (no cudaMalloc allowed)
__device__ int   g_lists[TT][NN];
__device__ int   g_counts[TT];
__device__ int   g_job;
// Pre-converted projection matrices: [t][jj 0-3=edge,4=node][hi/lo],
// 128 rows x 272 B padded tiles, hi then lo contiguous (4352 uint4).
__device__ uint4 g_prep[TT][5][2][2176];

// ---------------------------------------------------------------------------
__global__ void k_zero() {
    if (threadIdx.x < TT) g_counts[threadIdx.x] = 0;
    if (threadIdx.x == 0) g_job = 0;
}

// ---------------------------------------------------------------------------
#define A_BUF 17408            // per-buffer: hi 8704 + lo 8704
#define M_BUF 69632            // per-buffer: hi 34816 + lo 34816
#define SM_A  0                // 2 buffers: 34816
#define SM_M  34816            // 2 buffers: 139264 -> ends 174080
#define SM_NF 174080           // 32 x 132 floats = 16896 -> 190976
#define SM_ROWS 190976         // 32 ints -> 191104
#define SM_SS 191104           // 32 x 8 floats -> 192128
#define SM_JOB 192128
#define SMEM_BYTES 192160

__device__ __forceinline__ uint32_t pk(__nv_bfloat16 a, __nv_bfloat16 b) {
    __nv_bfloat162 t(a, b);
    return *(uint32_t*)&t;
}

__device__ __forceinline__ void split4(float4 v, uint2& hi, uint2& lo) {
    __nv_bfloat16 h0 = __float2bfloat16_rn(v.x); float l0 = v.x - __bfloat162float(h0);
    __nv_bfloat16 h1 = __float2bfloat16_rn(v.y); float l1 = v.y - __bfloat162float(h1);
    __nv_bfloat16 h2 = __float2bfloat16_rn(v.z); float l2 = v.z - __bfloat162float(h2);
    __nv_bfloat16 h3 = __float2bfloat16_rn(v.w); float l3 = v.w - __bfloat162float(h3);
    hi = make_uint2(pk(h0, h1), pk(h2, h3));
    lo = make_uint2(pk(__float2bfloat16_rn(l0), __float2bfloat16_rn(l1)),
                    pk(__float2bfloat16_rn(l2), __float2bfloat16_rn(l3)));
}

__device__ __forceinline__ void mma16816(float* c, const uint32_t* a,
                                         uint32_t b0, uint32_t b1) {
    asm volatile(
        "mma.sync.aligned.m16n8k16.row.col.f32.bf16.bf16.f32 "
        "{%0,%1,%2,%3}, {%4,%5,%6,%7}, {%8,%9}, {%0,%1,%2,%3};"
        : "+f"(c[0]), "+f"(c[1]), "+f"(c[2]), "+f"(c[3])
        : "r"(a[0]), "r"(a[1]), "r"(a[2]), "r"(a[3]), "r"(b0), "r"(b1));
}

__device__ __forceinline__ void ldm_x4(uint32_t* r, uint32_t saddr) {
    asm volatile("ldmatrix.sync.aligned.m8n8.x4.shared.b16 {%0,%1,%2,%3}, [%4];"
                 : "=r"(r[0]), "=r"(r[1]), "=r"(r[2]), "=r"(r[3]) : "r"(saddr));
}

__device__ __forceinline__ void cpasync16(uint32_t dst, const void* src) {
    asm volatile("cp.async.cg.shared.global [%0], [%1], 16;"
                 :: "r"(dst), "l"(src) : "memory");
}
#define CP_COMMIT() asm volatile("cp.async.commit_group;" ::: "memory")
#define CP_WAIT0()  asm volatile("cp.async.wait_group 0;" ::: "memory")

// ---------------------------------------------------------------------------
// Merged setup: blocks [0, sb) scatter nodes by type; blocks [sb, sb+20)
// pre-convert projection matrices to padded bf16 hi/lo tiles.
// ---------------------------------------------------------------------------
__global__ void k_setup(const int* __restrict__ mask, int n,
                        const float* __restrict__ node_proj,
                        const float* __restrict__ edge_proj) {
    const int sb = (n + 255) >> 8;
    const int b = blockIdx.x;
    const int tid = threadIdx.x;
    if (b < sb) {
        int i = b * 256 + tid;
        if (i < n) {
            int t = mask[i];
            int p = atomicAdd(&g_counts[t], 1);
            g_lists[t][p] = i;
        }
        return;
    }
    const int mat = b - sb;              // 0..19
    const int t = mat / 5, jj = mat % 5;
    const float* src = (jj == 4) ? node_proj + (size_t)t * FF * FF
                                 : edge_proj + ((size_t)t * TT + jj) * FF * FF;
    const int row = tid >> 1;
    const int c0  = (tid & 1) * 16;
    char* dh = (char*)g_prep[t][jj][0];
    char* dl = (char*)g_prep[t][jj][1];
    const float* s = src + (size_t)row * FF;
#pragma unroll
    for (int c4 = 0; c4 < 16; c4++) {
        float4 v = *(const float4*)(s + (c0 + c4) * 4);
        uint2 hi, lo;
        split4(v, hi, lo);
        *(uint2*)(dh + row * 272 + (c0 + c4) * 8) = hi;
        *(uint2*)(dl + row * 272 + (c0 + c4) * 8) = lo;
    }
}

// ---------------------------------------------------------------------------
// Staging helpers (512 threads).
// ---------------------------------------------------------------------------
__device__ __forceinline__ void issue_M(uint32_t sb, int buf, int t, int jj, int tid) {
    const uint4* src = g_prep[t][jj][0];
    uint32_t dst = sb + SM_M + buf * M_BUF;
#pragma unroll
    for (int s = 0; s < 8; s++) {
        int i = tid + s * 512;
        cpasync16(dst + i * 16, src + i);
    }
    {
        int i = tid + 4096;
        if (i < 4352) cpasync16(dst + i * 16, src + i);
    }
}

__device__ __forceinline__ void issue_A(float4* v, const int* rows,
                                        const float* __restrict__ base,
                                        size_t stride, int tid) {
    const int row = tid >> 4;
    const int c4 = (tid & 15) * 2;
    const int r = rows[row];
    if (r >= 0) {
        const float* src = base + (size_t)r * stride;
        v[0] = *(const float4*)(src + c4 * 4);
        v[1] = *(const float4*)(src + c4 * 4 + 4);
    } else {
        v[0] = make_float4(0.f, 0.f, 0.f, 0.f);
        v[1] = make_float4(0.f, 0.f, 0.f, 0.f);
    }
}

__device__ __forceinline__ void store_A(char* smem, int buf, const float4* v, int tid) {
    const int row = tid >> 4;
    const int c4 = (tid & 15) * 2;
    char* hb = smem + SM_A + buf * A_BUF;
    char* lb = hb + 8704;
    const uint32_t rb = (uint32_t)row * 272u;
#pragma unroll
    for (int q = 0; q < 2; q++) {
        uint2 hi, lo;
        split4(v[q], hi, lo);
        *(uint2*)(hb + rb + (c4 + q) * 8) = hi;
        *(uint2*)(lb + rb + (c4 + q) * 8) = lo;
    }
}

// ---------------------------------------------------------------------------
// Compute: warp tile 16m x 16n. SIX independent accumulator chains per warp
// (term x n-tile), k-loop unrolled x2 so next ldmatrix overlaps mma latency.
// ---------------------------------------------------------------------------
__device__ __forceinline__ void compute16(uint32_t aH, uint32_t aL,
                                          uint32_t bH, uint32_t bL,
                                          float hh[2][4], float lh[2][4],
                                          float hl[2][4]) {
#pragma unroll 2
    for (int k0 = 0; k0 < 8; k0++) {
        const uint32_t koff = (uint32_t)k0 * 32u;
        uint32_t ah[4], al[4], bh[4], bl[4];
        ldm_x4(ah, aH + koff);
        ldm_x4(al, aL + koff);
        ldm_x4(bh, bH + koff);
        ldm_x4(bl, bL + koff);
        mma16816(hh[0], ah, bh[0], bh[2]);
        mma16816(hh[1], ah, bh[1], bh[3]);
        mma16816(lh[0], al, bh[0], bh[2]);
        mma16816(lh[1], al, bh[1], bh[3]);
        mma16816(hl[0], ah, bl[0], bl[2]);
        mma16816(hl[1], ah, bl[1], bl[3]);
    }
}

// ---------------------------------------------------------------------------
// Persistent fused kernel, 32-row jobs, double-buffered pipelined staging.
// 16 warps: m-group = wid>>3 (2 x 16 rows), head = wid&7.
// ---------------------------------------------------------------------------
__global__ __launch_bounds__(512, 1) void k_fused(
    const float* __restrict__ feature,    // [N,F]
    const float* __restrict__ edge_fea,   // [N,T,F]
    float* __restrict__ out)              // [N,T,H]
{
    extern __shared__ char smem[];
    const int tid = threadIdx.x, wid = tid >> 5, lane = tid & 31;
    int*   rows = (int*)(smem + SM_ROWS);
    float* nf   = (float*)(smem + SM_NF);     // [32][132]
    float* ss   = (float*)(smem + SM_SS);     // [32][8]
    int*   jobp = (int*)(smem + SM_JOB);

    const int m0 = (wid >> 3) * 16;
    const int nwid = wid & 7;                 // head index
    const int n0 = nwid * 16;
    const int fr = lane >> 2, fc = lane & 3;
    const uint32_t laneoff = (uint32_t)(lane & 15) * 272u + (uint32_t)(lane >> 4) * 16u;
    const uint32_t sb = (uint32_t)(uint64_t)__cvta_generic_to_shared(smem);

    for (;;) {
        __syncthreads();                      // smem reuse + jobp
        if (tid == 0) *jobp = atomicAdd(&g_job, 1);
        __syncthreads();
        const int job = *jobp;
        if (job >= NJOBS) break;

        const int t = job & 3;
        const int chunk = job >> 2;
        const int cnt = g_counts[t];
        const int start = chunk * ROWS_J;
        if (start >= cnt) continue;

        if (tid < ROWS_J) {
            int idx = start + tid;
            rows[tid] = (idx < cnt) ? g_lists[t][idx] : -1;
        }
        issue_M(sb, 0, t, 4, tid);            // node matrix into buf 0
        CP_COMMIT();
        __syncthreads();                      // rows visible

        {   // phase-0 A staging
            float4 v[2];
            issue_A(v, rows, feature, FF, tid);
            store_A(smem, 0, v, tid);
        }
        CP_WAIT0();
        __syncthreads();

#pragma unroll 1
        for (int ph = 0; ph < 5; ph++) {
            const int cur = ph & 1, nxt = cur ^ 1;
            float4 v[2];
            if (ph < 4) {
                issue_M(sb, nxt, t, ph, tid); // phase ph+1 uses edge j=ph
                CP_COMMIT();
                issue_A(v, rows, edge_fea + ph * FF, (size_t)TT * FF, tid);
            }

            float hh[2][4], lh[2][4], hl[2][4];
#pragma unroll
            for (int nt = 0; nt < 2; nt++)
#pragma unroll
                for (int q = 0; q < 4; q++) {
                    hh[nt][q] = 0.f; lh[nt][q] = 0.f; hl[nt][q] = 0.f;
                }
            {
                const uint32_t aH = sb + SM_A + cur * A_BUF + (uint32_t)m0 * 272u + laneoff;
                const uint32_t bH = sb + SM_M + cur * M_BUF + (uint32_t)n0 * 272u + laneoff;
                compute16(aH, aH + 8704u, bH, bH + 34816u, hh, lh, hl);
            }
            float acc[2][4];
#pragma unroll
            for (int nt = 0; nt < 2; nt++)
#pragma unroll
                for (int q = 0; q < 4; q++)
                    acc[nt][q] = hh[nt][q] + lh[nt][q] + hl[nt][q];

            if (ph == 0) {
                // node result -> nf
#pragma unroll
                for (int half = 0; half < 2; half++) {
                    const int mrow = m0 + half * 8 + fr;
                    float* drow = nf + mrow * 132;
#pragma unroll
                    for (int nt = 0; nt < 2; nt++)
                        *(float2*)(drow + n0 + nt * 8 + fc * 2) =
                            make_float2(acc[nt][half * 2], acc[nt][half * 2 + 1]);
                }
            } else {
                // fused score for head nwid
#pragma unroll
                for (int half = 0; half < 2; half++) {
                    const int mrow = m0 + half * 8 + fr;
                    const float* nrow = nf + mrow * 132;
                    float p = acc[0][half * 2]     * nrow[n0 + fc * 2]
                            + acc[0][half * 2 + 1] * nrow[n0 + fc * 2 + 1]
                            + acc[1][half * 2]     * nrow[n0 + 8 + fc * 2]
                            + acc[1][half * 2 + 1] * nrow[n0 + 8 + fc * 2 + 1];
                    p += __shfl_xor_sync(0xffffffffu, p, 1);
                    p += __shfl_xor_sync(0xffffffffu, p, 2);
                    if (fc == 0) ss[mrow * 8 + nwid] = p * 0.25f;
                }
            }

            if (ph < 4) store_A(smem, nxt, v, tid);
            __syncthreads();                  // ss / nf / A-stage visible

            if (ph > 0) {
                const int j = ph - 1;
                if (tid < ROWS_J) {
                    int r = rows[tid];
                    if (r >= 0) {
                        float sv[HH];
                        float m = -1e30f;
#pragma unroll
                        for (int h = 0; h < HH; h++) { sv[h] = ss[tid * 8 + h]; m = fmaxf(m, sv[h]); }
                        float sum = 0.f;
#pragma unroll
                        for (int h = 0; h < HH; h++) { sv[h] = expf(sv[h] - m); sum += sv[h]; }
                        float inv = 1.f / sum;
                        float* dst = out + (size_t)r * (TT * HH) + j * HH;
#pragma unroll
                        for (int h = 0; h < HH; h += 4)
                            *(float4*)(dst + h) = make_float4(sv[h] * inv, sv[h + 1] * inv,
                                                              sv[h + 2] * inv, sv[h + 3] * inv);
                    }
                }
            }
            if (ph < 4) CP_WAIT0();
            __syncthreads();                  // ss reusable; M(nxt) visible
        }
    }
}

// ---------------------------------------------------------------------------
extern "C" void kernel_launch(void* const* d_in, const int* in_sizes, int n_in,
                              void* d_out, int out_size) {
    const float* feature   = (const float*)d_in[0];
    const float* edge_fea  = (const float*)d_in[1];
    const int*   mask      = (const int*)d_in[2];
    const float* node_proj = (const float*)d_in[3];
    const float* edge_proj = (const float*)d_in[4];
    float* out = (float*)d_out;

    const int n = in_sizes[2];

    static int smem_set = 0;
    if (!smem_set) {
        cudaFuncSetAttribute(k_fused, cudaFuncAttributeMaxDynamicSharedMemorySize, SMEM_BYTES);
        smem_set = 1;
    }

    k_zero<<<1, 32>>>();
    const int sb = (n + 255) / 256;
    k_setup<<<sb + 20, 256>>>(mask, n, node_proj, edge_proj);

    k_fused<<<152, 512, SMEM_BYTES>>>(feature, edge_fea, out);
}